// round 12
// baseline (speedup 1.0000x reference)
#include <cuda_runtime.h>
#include <cstdint>

// Covariance pooling: y[b] = (1/M) X Xᵀ - μ μᵀ, X = x[b] as [C=128, M=4096].
// tf32 mma.sync SYRK, in-CTA symmetry (3 of 4 64x64 tiles), LDG->reg->STS feed.
// R4/R5/R11 were bound by cp.async issue throughput (8 cyc/LDGSTS/SMSP =
// 2048 cyc/k-tile, exactly the measured wall). This version feeds SMEM with
// LDG.128 + STS.128 (floors ~4/2 cyc) through a 3-stage ring with 2-deep
// register staging; row sums accumulate in registers at load time.
// Kernel 1 (partial): 128 CTAs = 64 batches x 2 K-halves, 256 threads (8 warps):
//   w0/w1: tile(0,0) k8-steps {0,1}/{2,3}; w2/w3: tile(1,1) same; w4..w7:
//   tile(0,1), one k8-step each. 96 MMA/SMSP/k-tile, balanced.
// Kernel 2 (finish): 512 CTAs; combines K-halves, mean subtraction, mirrors
//   the off-diagonal tile into the lower triangle.

#define DINLINE __device__ __forceinline__

static constexpr int Bn = 64;
static constexpr int Cn = 128;
static constexpr int Mn = 4096;
static constexpr int KHALF = Mn / 2;       // 2048
static constexpr int KT = 32;              // k floats per tile
static constexpr int NKT = KHALF / KT;     // 64
static constexpr int PADB = 144;           // bytes per SMEM row (36 floats)
static constexpr int STAGE_B = Cn * PADB;  // 18432
static constexpr int SMEM_B = 3 * STAGE_B; // 55296 (covers 48KB combine area)

// tf32 truncation debias: 1/(1 - 2 * 2^-11 * (1/(2 ln 2)))
static constexpr float CORR = 1.00070466f;

__device__ float g_part[2 * Bn][3][64 * 64];   // [cta][0=d00,1=d11,2=off01]
__device__ float g_sums[2 * Bn][Cn];

DINLINE void mma_tf32(float d[4], const uint32_t a[4], uint32_t b0, uint32_t b1) {
    asm volatile(
        "mma.sync.aligned.m16n8k8.row.col.f32.tf32.tf32.f32 "
        "{%0,%1,%2,%3}, {%4,%5,%6,%7}, {%8,%9}, {%0,%1,%2,%3};"
        : "+f"(d[0]), "+f"(d[1]), "+f"(d[2]), "+f"(d[3])
        : "r"(a[0]), "r"(a[1]), "r"(a[2]), "r"(a[3]), "r"(b0), "r"(b1));
}
DINLINE void ldsm_x4(uint32_t r[4], uint32_t addr) {
    asm volatile("ldmatrix.sync.aligned.m8n8.x4.shared.b16 {%0,%1,%2,%3}, [%4];"
                 : "=r"(r[0]), "=r"(r[1]), "=r"(r[2]), "=r"(r[3]) : "r"(addr));
}
DINLINE uint32_t smem_u32(const void* p) {
    uint32_t a;
    asm("{ .reg .u64 t; cvta.to.shared.u64 t, %1; cvt.u32.u64 %0, t; }"
        : "=r"(a) : "l"(p));
    return a;
}

__global__ __launch_bounds__(256, 1)
void covpool_partial(const float* __restrict__ x) {
    extern __shared__ char smem[];
    const uint32_t sb = smem_u32(smem);

    const int t    = threadIdx.x;
    const int warp = t >> 5;
    const int lane = t & 31;
    const int cta  = blockIdx.x;        // 0..127
    const int s    = cta & 1;
    const int b    = cta >> 1;

    // loader: 2 threads per row, 64 B each per k-tile
    const int lrow = t >> 1;
    const int lh   = t & 1;
    const float* xsrc = x + (size_t)b * Cn * Mn + (size_t)lrow * Mn
                          + (size_t)s * KHALF + lh * 16;
    const uint32_t ldst = (uint32_t)(lrow * PADB + lh * 64);

    // warp job: tile (wm, wn) + k8-step set
    int wm, wn, ks0;
    bool two_steps;
    if (warp < 4) {
        wm = (warp >> 1) * 64; wn = wm;          // diag tiles
        ks0 = (warp & 1) * 2;  two_steps = true;
    } else {
        wm = 0; wn = 64;                          // off-diag tile
        ks0 = warp - 4;        two_steps = false;
    }

    const uint32_t aoff = (uint32_t)((wm + (lane & 15)) * PADB + (lane >> 4) * 16);
    const uint32_t boff = (uint32_t)((wn + (lane & 7) + ((lane >> 4) * 8)) * PADB
                                     + ((lane >> 3) & 1) * 16);
    const int g  = lane >> 2;
    const int tg = lane & 3;

    float acc[4][8][4];
#pragma unroll
    for (int im = 0; im < 4; im++)
#pragma unroll
        for (int in = 0; in < 8; in++)
#pragma unroll
            for (int j = 0; j < 4; j++) acc[im][in][j] = 0.0f;

    float rowsum = 0.0f;
    float4 Ra[4], Rb[4];                    // 2-deep register staging

    auto ldg_tile = [&](int kt_, float4 (&R)[4]) {
        const float* sp = xsrc + (size_t)kt_ * KT;
#pragma unroll
        for (int i = 0; i < 4; i++) {
            R[i] = __ldg((const float4*)(sp + i * 4));
            rowsum += R[i].x + R[i].y + R[i].z + R[i].w;
        }
    };
    auto sts_tile = [&](int stage, const float4 (&R)[4]) {
        char* d = smem + stage * STAGE_B + ldst;
#pragma unroll
        for (int i = 0; i < 4; i++) *(float4*)(d + i * 16) = R[i];
    };

    // prologue: tiles 0,1 into regs; tile 0 into stage 0
    ldg_tile(0, Ra);
    ldg_tile(1, Rb);
    sts_tile(0, Ra);

    int c_cur = 0, c_nxt = 1;
    for (int kt = 0; kt < NKT; kt++) {
        // STS tile kt+1 into next stage; LDG tile kt+2 into freed staging regs
        if ((kt & 1) == 0) {
            if (kt + 1 < NKT) sts_tile(c_nxt, Rb);
            if (kt + 2 < NKT) ldg_tile(kt + 2, Ra);
        } else {
            if (kt + 1 < NKT) sts_tile(c_nxt, Ra);
            if (kt + 2 < NKT) ldg_tile(kt + 2, Rb);
        }
        __syncthreads();

        const uint32_t base = sb + (uint32_t)(c_cur * STAGE_B);
        auto mma_step = [&](uint32_t k0) {
            uint32_t A[4][4], Bf[4][4];
#pragma unroll
            for (int im = 0; im < 4; im++)
                ldsm_x4(A[im], base + aoff + im * 16 * PADB + k0);
#pragma unroll
            for (int jn = 0; jn < 4; jn++)
                ldsm_x4(Bf[jn], base + boff + jn * 16 * PADB + k0);
#pragma unroll
            for (int im = 0; im < 4; im++)
#pragma unroll
                for (int jn = 0; jn < 4; jn++) {
                    mma_tf32(acc[im][2 * jn],     A[im], Bf[jn][0], Bf[jn][1]);
                    mma_tf32(acc[im][2 * jn + 1], A[im], Bf[jn][2], Bf[jn][3]);
                }
        };
        const uint32_t kb0 = (uint32_t)(ks0 * 32);
        if (two_steps) { mma_step(kb0); mma_step(kb0 + 32); }
        else           { mma_step(kb0); }

        c_cur = (c_cur == 2) ? 0 : c_cur + 1;
        c_nxt = (c_nxt == 2) ? 0 : c_nxt + 1;
    }

    // row sums (pairs of threads share a row; exact fp32)
    rowsum += __shfl_xor_sync(0xffffffffu, rowsum, 1);
    if (lh == 0) g_sums[cta][lrow] = rowsum;

    // ---- combine warp partials ----
    __syncthreads();
    float* cs = (float*)smem;
    auto dump = [&](int region) {
        float4* d = (float4*)(cs + (size_t)region * 4096) + lane * 32;
#pragma unroll
        for (int im = 0; im < 4; im++)
#pragma unroll
            for (int in = 0; in < 8; in++)
                d[im * 8 + in] = make_float4(acc[im][in][0], acc[im][in][1],
                                             acc[im][in][2], acc[im][in][3]);
    };
    auto reduce = [&](int region) {
        const float4* sp = (const float4*)(cs + (size_t)region * 4096) + lane * 32;
#pragma unroll
        for (int im = 0; im < 4; im++)
#pragma unroll
            for (int in = 0; in < 8; in++) {
                float4 v = sp[im * 8 + in];
                acc[im][in][0] += v.x; acc[im][in][1] += v.y;
                acc[im][in][2] += v.z; acc[im][in][3] += v.w;
            }
    };

    if (warp == 1) dump(0);
    else if (warp == 3) dump(1);
    else if (warp == 5) dump(2);
    __syncthreads();
    if (warp == 0) reduce(0);
    else if (warp == 2) reduce(1);
    else if (warp == 4) reduce(2);
    __syncthreads();
    if (warp == 6) dump(0);
    else if (warp == 7) dump(1);
    __syncthreads();
    if (warp == 4) { reduce(0); reduce(1); }

    if (warp == 0 || warp == 2 || warp == 4) {
        const int tileIdx = (warp == 0) ? 0 : (warp == 2) ? 1 : 2;
        float* gp = g_part[cta][tileIdx];
#pragma unroll
        for (int im = 0; im < 4; im++) {
            const int r0 = im * 16 + g;
#pragma unroll
            for (int in = 0; in < 8; in++) {
                const int c0 = in * 8 + 2 * tg;
                *(float2*)(gp + r0 * 64 + c0) =
                    make_float2(acc[im][in][0], acc[im][in][1]);
                *(float2*)(gp + (r0 + 8) * 64 + c0) =
                    make_float2(acc[im][in][2], acc[im][in][3]);
            }
        }
    }
}

__global__ __launch_bounds__(256, 2)
void covpool_finish(float* __restrict__ y) {
    __shared__ float mu[Cn];
    const int t   = threadIdx.x;
    const int b   = blockIdx.x >> 3;
    const int sub = blockIdx.x & 7;
    const int q    = sub >> 1;
    const int half = sub & 1;
    if (t < Cn)
        mu[t] = (g_sums[2 * b][t] + g_sums[2 * b + 1][t]) * (1.0f / (float)Mn);
    __syncthreads();

    const float a = CORR * (1.0f / (float)Mn);
    float* yb = y + (size_t)b * Cn * Cn;

    if (q == 0 || q == 3) {                 // diagonal quadrants
        const int d = (q == 0) ? 0 : 64;
        const int ti = (q == 0) ? 0 : 1;
        const float4* G0 = (const float4*)g_part[2 * b][ti];
        const float4* G1 = (const float4*)g_part[2 * b + 1][ti];
#pragma unroll
        for (int k = 0; k < 2; k++) {
            const int e4 = t + (half * 2 + k) * 256;   // float4 idx in [0,1024)
            const int i  = e4 >> 4;
            const int j4 = e4 & 15;
            float4 p0 = G0[e4], p1 = G1[e4];
            const float mr = mu[d + i];
            const float4 m = ((const float4*)mu)[(d >> 2) + j4];
            float4 o;
            o.x = (p0.x + p1.x) * a - mr * m.x;
            o.y = (p0.y + p1.y) * a - mr * m.y;
            o.z = (p0.z + p1.z) * a - mr * m.z;
            o.w = (p0.w + p1.w) * a - mr * m.w;
            ((float4*)(yb + (size_t)(d + i) * Cn + d))[j4] = o;
        }
    } else if (q == 1) {                    // upper-right
        const float4* G0 = (const float4*)g_part[2 * b][2];
        const float4* G1 = (const float4*)g_part[2 * b + 1][2];
#pragma unroll
        for (int k = 0; k < 2; k++) {
            const int e4 = t + (half * 2 + k) * 256;
            const int i  = e4 >> 4;
            const int j4 = e4 & 15;
            float4 p0 = G0[e4], p1 = G1[e4];
            const float mr = mu[i];
            const float4 m = ((const float4*)mu)[16 + j4];
            float4 o;
            o.x = (p0.x + p1.x) * a - mr * m.x;
            o.y = (p0.y + p1.y) * a - mr * m.y;
            o.z = (p0.z + p1.z) * a - mr * m.z;
            o.w = (p0.w + p1.w) * a - mr * m.w;
            ((float4*)(yb + (size_t)i * Cn + 64))[j4] = o;
        }
    } else {                                // lower-left: transposed off-diag
        const float* Ga = g_part[2 * b][2];
        const float* Gb = g_part[2 * b + 1][2];
#pragma unroll
        for (int k = 0; k < 2; k++) {
            const int e4 = t + (half * 2 + k) * 256;
            const int jj = e4 >> 4;          // out row 64+jj
            const int i0 = (e4 & 15) * 4;    // out cols i0..i0+3
            const float mr = mu[64 + jj];
            float4 o;
            o.x = (Ga[(i0 + 0) * 64 + jj] + Gb[(i0 + 0) * 64 + jj]) * a - mr * mu[i0 + 0];
            o.y = (Ga[(i0 + 1) * 64 + jj] + Gb[(i0 + 1) * 64 + jj]) * a - mr * mu[i0 + 1];
            o.z = (Ga[(i0 + 2) * 64 + jj] + Gb[(i0 + 2) * 64 + jj]) * a - mr * mu[i0 + 2];
            o.w = (Ga[(i0 + 3) * 64 + jj] + Gb[(i0 + 3) * 64 + jj]) * a - mr * mu[i0 + 3];
            *(float4*)(yb + (size_t)(64 + jj) * Cn + i0) = o;
        }
    }
}

extern "C" void kernel_launch(void* const* d_in, const int* in_sizes, int n_in,
                              void* d_out, int out_size) {
    (void)in_sizes; (void)n_in; (void)out_size;
    const float* x = (const float*)d_in[0];
    float* y = (float*)d_out;
    cudaFuncSetAttribute(covpool_partial,
                         cudaFuncAttributeMaxDynamicSharedMemorySize, SMEM_B);
    covpool_partial<<<2 * Bn, 256, SMEM_B>>>(x);
    covpool_finish<<<8 * Bn, 256>>>(y);
}

// round 13
// speedup vs baseline: 1.4418x; 1.4418x over previous
#include <cuda_runtime.h>
#include <cstdint>

// Covariance pooling: y[b] = (1/M) X Xᵀ - μ μᵀ, X = x[b] as [C=128, M=4096].
// R4's proven tf32 kernel with K split 4 ways -> 256 CTAs so each SM hosts TWO
// independent CTAs (occupancy 2). Hypothesis: R4/R5/R11's ~2050 cyc/k-tile is
// barrier/latency idle time in a single resident CTA's lock-step pipeline;
// two co-resident CTAs interleave phases and fill the bubbles.
// Kernel 1 (partial): 256 CTAs = 64 batches x 4 K-quarters; 128 threads; 4
//   warps of 64x64 tiles; cp.async 3-stage pipeline; raw-fp32 into tf32
//   mma.sync (debias CORR); exact fp32 row sums in-pipeline.
// Kernel 2 (finish): 512 CTAs combine 4 K-quarters + mean subtraction.

#define DINLINE __device__ __forceinline__

static constexpr int Bn = 64;
static constexpr int Cn = 128;
static constexpr int Mn = 4096;
static constexpr int KSPLIT = 4;
static constexpr int KQ = Mn / KSPLIT;     // 1024
static constexpr int KT = 32;              // k floats per tile
static constexpr int NKT = KQ / KT;        // 32 tiles
static constexpr int PADB = 144;           // bytes per SMEM row (36 floats)
static constexpr int STAGES = 3;
static constexpr int STAGE_B = Cn * PADB;  // 18432
static constexpr int SMEM_B = STAGES * STAGE_B;  // 55296 -> 2 CTAs/SM fit

// tf32 truncation debias: 1/(1 - 2 * 2^-11 * (1/(2 ln 2)))
static constexpr float CORR = 1.00070466f;

__device__ float g_part[KSPLIT * Bn][Cn * Cn];   // 16 MB scratch
__device__ float g_sums[KSPLIT * Bn][Cn];

DINLINE void mma_tf32(float d[4], const uint32_t a[4], uint32_t b0, uint32_t b1) {
    asm volatile(
        "mma.sync.aligned.m16n8k8.row.col.f32.tf32.tf32.f32 "
        "{%0,%1,%2,%3}, {%4,%5,%6,%7}, {%8,%9}, {%0,%1,%2,%3};"
        : "+f"(d[0]), "+f"(d[1]), "+f"(d[2]), "+f"(d[3])
        : "r"(a[0]), "r"(a[1]), "r"(a[2]), "r"(a[3]), "r"(b0), "r"(b1));
}
DINLINE void ldsm_x4(uint32_t r[4], uint32_t addr) {
    asm volatile("ldmatrix.sync.aligned.m8n8.x4.shared.b16 {%0,%1,%2,%3}, [%4];"
                 : "=r"(r[0]), "=r"(r[1]), "=r"(r[2]), "=r"(r[3]) : "r"(addr));
}
DINLINE uint32_t smem_u32(const void* p) {
    uint32_t a;
    asm("{ .reg .u64 t; cvta.to.shared.u64 t, %1; cvt.u32.u64 %0, t; }"
        : "=r"(a) : "l"(p));
    return a;
}
DINLINE void cp16(uint32_t dst, const void* src) {
    asm volatile("cp.async.cg.shared.global [%0], [%1], 16;"
                 :: "r"(dst), "l"(src) : "memory");
}
DINLINE void cp_commit() { asm volatile("cp.async.commit_group;" ::: "memory"); }
template <int N> DINLINE void cp_wait() {
    asm volatile("cp.async.wait_group %0;" :: "n"(N) : "memory");
}

__global__ __launch_bounds__(128, 2)
void covpool_partial(const float* __restrict__ x) {
    extern __shared__ char smem[];
    const uint32_t sb = smem_u32(smem);

    const int t    = threadIdx.x;
    const int warp = t >> 5;
    const int lane = t & 31;
    const int cta  = blockIdx.x;        // 0..255
    const int s    = cta & 3;           // K-quarter
    const int b    = cta >> 2;

    // loader: one row per thread, 128 B per k-tile
    const float* xrow = x + (size_t)b * Cn * Mn + (size_t)t * Mn + (size_t)s * KQ;
    const uint32_t ldst = (uint32_t)(t * PADB);

    // warp tile 64x64, 2x2 warp grid
    const int wm = (warp & 1) * 64;
    const int wn = (warp >> 1) * 64;
    const int g  = lane >> 2;
    const int tg = lane & 3;

    const uint32_t aoff = (uint32_t)((wm + (lane & 15)) * PADB + (lane >> 4) * 16);
    const uint32_t boff = (uint32_t)((wn + (lane & 7) + ((lane >> 4) * 8)) * PADB
                                     + ((lane >> 3) & 1) * 16);

    float acc[4][8][4];
#pragma unroll
    for (int im = 0; im < 4; im++)
#pragma unroll
        for (int in = 0; in < 8; in++)
#pragma unroll
            for (int j = 0; j < 4; j++) acc[im][in][j] = 0.0f;

    float rowsum = 0.0f;

    // prologue: stages 0,1
#pragma unroll
    for (int p = 0; p < STAGES - 1; p++) {
        const uint32_t d0 = sb + p * STAGE_B + ldst;
        const float* src = xrow + p * KT;
#pragma unroll
        for (int i = 0; i < 8; i++) cp16(d0 + i * 16, src + i * 4);
        cp_commit();
    }

    int cur = 0, iss = STAGES - 1;
    for (int kt = 0; kt < NKT; kt++) {
        cp_wait<STAGES - 2>();
        __syncthreads();
        if (kt + STAGES - 1 < NKT) {
            const uint32_t d0 = sb + iss * STAGE_B + ldst;
            const float* src = xrow + (kt + STAGES - 1) * KT;
#pragma unroll
            for (int i = 0; i < 8; i++) cp16(d0 + i * 16, src + i * 4);
        }
        cp_commit();

        const uint32_t base = sb + cur * STAGE_B;

        // exact fp32 row sum of this thread's own row
#pragma unroll
        for (int i = 0; i < 8; i++) {
            float4 v = *(const float4*)(smem + cur * STAGE_B + t * PADB + i * 16);
            rowsum += v.x + v.y + v.z + v.w;
        }

#pragma unroll
        for (int ks = 0; ks < 4; ks++) {
            const uint32_t k0 = ks * 32;   // bytes within row
            uint32_t A[4][4], Bf[4][4];
#pragma unroll
            for (int im = 0; im < 4; im++)
                ldsm_x4(A[im], base + aoff + im * 16 * PADB + k0);
#pragma unroll
            for (int jn = 0; jn < 4; jn++)
                ldsm_x4(Bf[jn], base + boff + jn * 16 * PADB + k0);
#pragma unroll
            for (int im = 0; im < 4; im++)
#pragma unroll
                for (int jn = 0; jn < 4; jn++) {
                    mma_tf32(acc[im][2 * jn],     A[im], Bf[jn][0], Bf[jn][1]);
                    mma_tf32(acc[im][2 * jn + 1], A[im], Bf[jn][2], Bf[jn][3]);
                }
        }

        cur = (cur + 1 == STAGES) ? 0 : cur + 1;
        iss = (iss + 1 == STAGES) ? 0 : iss + 1;
    }

    // epilogue: partial Gram + row sums to scratch
    float* gp = g_part[cta];
#pragma unroll
    for (int im = 0; im < 4; im++) {
        const int r0 = wm + im * 16 + g;
#pragma unroll
        for (int in = 0; in < 8; in++) {
            const int c0 = wn + in * 8 + 2 * tg;
            *(float2*)(gp + (size_t)r0 * Cn + c0) =
                make_float2(acc[im][in][0], acc[im][in][1]);
            *(float2*)(gp + (size_t)(r0 + 8) * Cn + c0) =
                make_float2(acc[im][in][2], acc[im][in][3]);
        }
    }
    g_sums[cta][t] = rowsum;
}

__global__ __launch_bounds__(256, 2)
void covpool_finish(float* __restrict__ y) {
    __shared__ float mu[Cn];
    const int t   = threadIdx.x;
    const int b   = blockIdx.x >> 3;
    const int q   = blockIdx.x & 7;
    if (t < Cn)
        mu[t] = (g_sums[4 * b][t] + g_sums[4 * b + 1][t]
               + g_sums[4 * b + 2][t] + g_sums[4 * b + 3][t]) * (1.0f / (float)Mn);
    __syncthreads();

    const float4* G0 = (const float4*)g_part[4 * b];
    const float4* G1 = (const float4*)g_part[4 * b + 1];
    const float4* G2 = (const float4*)g_part[4 * b + 2];
    const float4* G3 = (const float4*)g_part[4 * b + 3];
    float4* out = (float4*)(y + (size_t)b * Cn * Cn);
    const float4* mu4 = (const float4*)mu;
    const float a = CORR * (1.0f / (float)Mn);
#pragma unroll
    for (int j = 0; j < 2; j++) {
        const int idx = q * 512 + t + j * 256;    // float4 index in [0,4096)
        const int r   = idx >> 5;
        const float mr = mu[r];
        const float4 m = mu4[idx & 31];
        const float4 p0 = G0[idx];
        const float4 p1 = G1[idx];
        const float4 p2 = G2[idx];
        const float4 p3 = G3[idx];
        float4 o;
        o.x = ((p0.x + p1.x) + (p2.x + p3.x)) * a - mr * m.x;
        o.y = ((p0.y + p1.y) + (p2.y + p3.y)) * a - mr * m.y;
        o.z = ((p0.z + p1.z) + (p2.z + p3.z)) * a - mr * m.z;
        o.w = ((p0.w + p1.w) + (p2.w + p3.w)) * a - mr * m.w;
        out[idx] = o;
    }
}

extern "C" void kernel_launch(void* const* d_in, const int* in_sizes, int n_in,
                              void* d_out, int out_size) {
    (void)in_sizes; (void)n_in; (void)out_size;
    const float* x = (const float*)d_in[0];
    float* y = (float*)d_out;
    cudaFuncSetAttribute(covpool_partial,
                         cudaFuncAttributeMaxDynamicSharedMemorySize, SMEM_B);
    covpool_partial<<<KSPLIT * Bn, 128, SMEM_B>>>(x);
    covpool_finish<<<8 * Bn, 256>>>(y);
}